// round 8
// baseline (speedup 1.0000x reference)
#include <cuda_runtime.h>
#include <math.h>

// Problem shape (fixed by the dataset)
#define B_    16
#define S_    8192
#define QDIM  1024
#define KDIM  256
#define FLOAT_MIN_V (-100000.0f)

#define CHUNKS 64
#define SCHUNK (S_ / CHUNKS)   // 128

// Scratch (no allocations allowed in kernel_launch)
__device__ float g_qp[B_ * KDIM];                    // projected query + bias, [B,K]
__device__ float g_partial[B_ * CHUNKS * KDIM];      // per-chunk ctx partials
__device__ float g_lsum[B_ * CHUNKS];                // per-chunk sum of exp weights
__device__ float g_invl[B_];                         // 1 / total softmax denom

// HW tanh (sm_75+): MUFU-class, abs err ~5e-4; measured rel_err impact 1.6e-6.
__device__ __forceinline__ float tanh_hw(float x)
{
    float y;
    asm("tanh.approx.f32 %0, %1;" : "=f"(y) : "f"(x));
    return y;
}

// ---------------------------------------------------------------------------
// Kernel 1: qp[b,k] = b_attr[k] + sum_q query[b,q] * W[k,q]
// one warp per (b,k); W row contiguous over q -> coalesced float4 loads
// ---------------------------------------------------------------------------
__global__ void k_proj(const float* __restrict__ query,
                       const float* __restrict__ W,
                       const float* __restrict__ bvec)
{
    int gw   = (blockIdx.x * blockDim.x + threadIdx.x) >> 5;
    int lane = threadIdx.x & 31;
    if (gw >= B_ * KDIM) return;
    int b = gw / KDIM;
    int k = gw % KDIM;

    const float4* qrow = (const float4*)(query + (size_t)b * QDIM);
    const float4* wrow = (const float4*)(W + (size_t)k * QDIM);

    float acc = 0.f;
#pragma unroll
    for (int j = 0; j < QDIM / (32 * 4); j++) {      // 8 iters
        float4 q4 = qrow[lane + j * 32];
        float4 w4 = wrow[lane + j * 32];
        acc += q4.x * w4.x + q4.y * w4.y + q4.z * w4.z + q4.w * w4.w;
    }
#pragma unroll
    for (int o = 16; o; o >>= 1) acc += __shfl_xor_sync(0xFFFFFFFFu, acc, o);
    if (lane == 0) g_qp[b * KDIM + k] = acc + bvec[k];
}

// ---------------------------------------------------------------------------
// Kernel 2 (FUSED): per (b, s-chunk) block of 256 threads:
//   Phase A: energies for 128 rows (warp-per-row, 16 rows/warp, 2-row batched
//            loads), w = exp(mask*e + (1-mask)*MIN) -> smem + global scores
//            (unnormalized; rescaled by k_rescale).
//            Safe without max-subtraction: |e| <= sum|V_attr| <= 16.
//   Phase B: ctx_c = sum_s w_s * values[s,:] via float4-column scheme
//            (thread owns col t&63, rows (t>>6)+4j), plus l_c = sum_s w_s.
// ---------------------------------------------------------------------------
__global__ void __launch_bounds__(256) k_fused(const float* __restrict__ keys,
                                               const float* __restrict__ values,
                                               const float* __restrict__ mask,
                                               const float* __restrict__ Vvec,
                                               float* __restrict__ scores)
{
    int b = blockIdx.x / CHUNKS;
    int c = blockIdx.x % CHUNKS;
    int t = threadIdx.x;                 // 0..255
    int lane = t & 31;
    int wid  = t >> 5;                   // 0..7
    int s0 = c * SCHUNK;

    __shared__ float  sw[SCHUNK];        // exp weights for the tile
    __shared__ float4 red4[256];

    // Per-batch constants into registers (L2/L1-resident after first wave)
    const float* qp = g_qp + b * KDIM;
    float4 qv0 = *(const float4*)(qp + lane * 4);
    float4 qv1 = *(const float4*)(qp + lane * 4 + 128);
    float4 vv0 = *(const float4*)(Vvec + lane * 4);
    float4 vv1 = *(const float4*)(Vvec + lane * 4 + 128);

    // ---------------- Phase A: energies -> weights ----------------
    // warp wid handles tile rows [wid*16, wid*16+16), 2 rows per iteration
    {
        int rbase = wid * 16;
        const float* krow = keys + ((size_t)b * S_ + s0 + rbase) * KDIM;
#pragma unroll 2
        for (int i = 0; i < 16; i += 2) {
            const float* r0p = krow + (size_t)i * KDIM;
            const float* r1p = krow + (size_t)(i + 1) * KDIM;
            // 4 LDG.128 in flight per lane before any math
            float4 k00 = *(const float4*)(r0p + lane * 4);
            float4 k01 = *(const float4*)(r0p + lane * 4 + 128);
            float4 k10 = *(const float4*)(r1p + lane * 4);
            float4 k11 = *(const float4*)(r1p + lane * 4 + 128);

            float e0 = 0.f, e1 = 0.f;
            e0 += tanh_hw(k00.x + qv0.x) * vv0.x;
            e0 += tanh_hw(k00.y + qv0.y) * vv0.y;
            e0 += tanh_hw(k00.z + qv0.z) * vv0.z;
            e0 += tanh_hw(k00.w + qv0.w) * vv0.w;
            e0 += tanh_hw(k01.x + qv1.x) * vv1.x;
            e0 += tanh_hw(k01.y + qv1.y) * vv1.y;
            e0 += tanh_hw(k01.z + qv1.z) * vv1.z;
            e0 += tanh_hw(k01.w + qv1.w) * vv1.w;

            e1 += tanh_hw(k10.x + qv0.x) * vv0.x;
            e1 += tanh_hw(k10.y + qv0.y) * vv0.y;
            e1 += tanh_hw(k10.z + qv0.z) * vv0.z;
            e1 += tanh_hw(k10.w + qv0.w) * vv0.w;
            e1 += tanh_hw(k11.x + qv1.x) * vv1.x;
            e1 += tanh_hw(k11.y + qv1.y) * vv1.y;
            e1 += tanh_hw(k11.z + qv1.z) * vv1.z;
            e1 += tanh_hw(k11.w + qv1.w) * vv1.w;

#pragma unroll
            for (int o = 16; o; o >>= 1) {
                e0 += __shfl_xor_sync(0xFFFFFFFFu, e0, o);
                e1 += __shfl_xor_sync(0xFFFFFFFFu, e1, o);
            }

            if (lane == 0) {
                size_t gs = (size_t)b * S_ + s0 + rbase + i;
                float m0 = mask[gs];
                float m1 = mask[gs + 1];
                float w0 = __expf(m0 * e0 + (1.0f - m0) * FLOAT_MIN_V);
                float w1 = __expf(m1 * e1 + (1.0f - m1) * FLOAT_MIN_V);
                sw[rbase + i]     = w0;
                sw[rbase + i + 1] = w1;
                scores[gs]     = w0;   // unnormalized; rescaled later
                scores[gs + 1] = w1;
            }
        }
    }
    __syncthreads();

    // ---------------- Phase B: weighted value accumulation ----------------
    int col = t & 63;                    // float4 column within row
    int r0  = t >> 6;                    // 0..3 row phase
    const float4* vp = (const float4*)(values + ((size_t)b * S_ + s0) * KDIM) + col;

    float4 a0 = make_float4(0.f, 0.f, 0.f, 0.f);
    float4 a1 = make_float4(0.f, 0.f, 0.f, 0.f);
    float4 a2 = make_float4(0.f, 0.f, 0.f, 0.f);
    float4 a3 = make_float4(0.f, 0.f, 0.f, 0.f);

#pragma unroll 2
    for (int jj = 0; jj < 32; jj += 4) {
        int r_0 = r0 + (jj + 0) * 4;
        int r_1 = r0 + (jj + 1) * 4;
        int r_2 = r0 + (jj + 2) * 4;
        int r_3 = r0 + (jj + 3) * 4;
        float4 v0 = vp[(size_t)r_0 * (KDIM / 4)];
        float4 v1 = vp[(size_t)r_1 * (KDIM / 4)];
        float4 v2 = vp[(size_t)r_2 * (KDIM / 4)];
        float4 v3 = vp[(size_t)r_3 * (KDIM / 4)];
        float s_0 = sw[r_0], s_1 = sw[r_1], s_2 = sw[r_2], s_3 = sw[r_3];
        a0.x += v0.x * s_0; a0.y += v0.y * s_0; a0.z += v0.z * s_0; a0.w += v0.w * s_0;
        a1.x += v1.x * s_1; a1.y += v1.y * s_1; a1.z += v1.z * s_1; a1.w += v1.w * s_1;
        a2.x += v2.x * s_2; a2.y += v2.y * s_2; a2.z += v2.z * s_2; a2.w += v2.w * s_2;
        a3.x += v3.x * s_3; a3.y += v3.y * s_3; a3.z += v3.z * s_3; a3.w += v3.w * s_3;
    }

    float4 acc;
    acc.x = (a0.x + a1.x) + (a2.x + a3.x);
    acc.y = (a0.y + a1.y) + (a2.y + a3.y);
    acc.z = (a0.z + a1.z) + (a2.z + a3.z);
    acc.w = (a0.w + a1.w) + (a2.w + a3.w);
    red4[t] = acc;

    // l_c reduction by warp 0 (sw is stable; red4[t] already written by this warp)
    float lc = 0.f;
    if (wid == 0) {
        lc = sw[lane] + sw[lane + 32] + sw[lane + 64] + sw[lane + 96];
#pragma unroll
        for (int o = 16; o; o >>= 1) lc += __shfl_xor_sync(0xFFFFFFFFu, lc, o);
    }
    __syncthreads();

    if (t < 64) {
        float4 p0 = red4[t];
        float4 p1 = red4[t + 64];
        float4 p2 = red4[t + 128];
        float4 p3 = red4[t + 192];
        float4 r;
        r.x = (p0.x + p1.x) + (p2.x + p3.x);
        r.y = (p0.y + p1.y) + (p2.y + p3.y);
        r.z = (p0.z + p1.z) + (p2.z + p3.z);
        r.w = (p0.w + p1.w) + (p2.w + p3.w);
        ((float4*)(g_partial + ((size_t)b * CHUNKS + c) * KDIM))[t] = r;
    }
    if (t == 0) g_lsum[b * CHUNKS + c] = lc;
}

// ---------------------------------------------------------------------------
// Kernel 3: finalize — ctx[b,k] = (sum_c partial) / (sum_c l_c); store 1/l.
// ---------------------------------------------------------------------------
__global__ void k_finalize(float* __restrict__ ctx)
{
    __shared__ float sl[CHUNKS];
    __shared__ float s_inv;
    int b = blockIdx.x;
    int k = threadIdx.x;                 // 0..255

    if (k < CHUNKS) sl[k] = g_lsum[b * CHUNKS + k];

    float acc = 0.f;
#pragma unroll
    for (int c = 0; c < CHUNKS; c++)
        acc += g_partial[((size_t)b * CHUNKS + c) * KDIM + k];

    __syncthreads();
    if (k == 0) {
        float l = 0.f;
#pragma unroll
        for (int c = 0; c < CHUNKS; c++) l += sl[c];
        float inv = 1.0f / l;
        g_invl[b] = inv;
        s_inv = inv;
    }
    __syncthreads();
    ctx[b * KDIM + k] = acc * s_inv;
}

// ---------------------------------------------------------------------------
// Kernel 4: rescale unnormalized scores in place: scores *= 1/l[b]
// float4 per thread; b constant within a float4 (S_ % 4 == 0).
// ---------------------------------------------------------------------------
__global__ void k_rescale(float* __restrict__ scores)
{
    int idx = blockIdx.x * blockDim.x + threadIdx.x;     // float4 index
    int b = (idx * 4) / S_;
    float inv = g_invl[b];
    float4 v = ((float4*)scores)[idx];
    v.x *= inv; v.y *= inv; v.z *= inv; v.w *= inv;
    ((float4*)scores)[idx] = v;
}

// ---------------------------------------------------------------------------
// Launch
// inputs (metadata order): query, keys, values, kv_mask, W_attr, b_attr, V_attr
// output: [scores (B*S) | ctx (B*K)]
// ---------------------------------------------------------------------------
extern "C" void kernel_launch(void* const* d_in, const int* in_sizes, int n_in,
                              void* d_out, int out_size)
{
    const float* query = (const float*)d_in[0];
    const float* keys  = (const float*)d_in[1];
    const float* values= (const float*)d_in[2];
    const float* mask  = (const float*)d_in[3];
    const float* W     = (const float*)d_in[4];
    const float* bvec  = (const float*)d_in[5];
    const float* Vvec  = (const float*)d_in[6];

    float* out    = (float*)d_out;
    float* scores = out;                     // B*S
    float* ctx    = out + (size_t)B_ * S_;   // B*K

    // 1) query projection: B*K warps, 8 warps/block
    {
        int warps = B_ * KDIM;
        int blocks = (warps * 32 + 255) / 256;
        k_proj<<<blocks, 256>>>(query, W, bvec);
    }
    // 2) fused energies + exp + weighted values (split-KV, no max needed)
    k_fused<<<B_ * CHUNKS, 256>>>(keys, values, mask, Vvec, scores);
    // 3) finalize ctx + 1/l
    k_finalize<<<B_, KDIM>>>(ctx);
    // 4) normalize scores
    k_rescale<<<(B_ * S_ / 4) / 256, 256>>>(scores);
}